// round 11
// baseline (speedup 1.0000x reference)
#include <cuda_runtime.h>
#include <math_constants.h>

// Problem constants
#define NSL     24
#define BB      16
#define CCH     512
#define HWN     256          // H*W
#define FEAT_IN 1024
#define CLASSES 3
#define CG      16           // c-values per CTA (2 per warp, 8 warps)
#define CTAS_PER_B (CCH / CG)       // 32
#define GRID    (BB * CTAS_PER_B)   // 512
#define SLICE_STRIDE ((size_t)BB * CCH * HWN)   // floats per slice (2M)

// Persistent scratch (zero at module load; each launch restores it to zero).
__device__ float        g_acc[BB * CLASSES];
__device__ unsigned int g_count[BB];

// Fused kernel: 512 CTAs x 256 threads. Each warp owns a CHANNEL PAIR
// (c, c+1): every slice visit reads 2KB contiguous (4 LDG.128/lane) instead
// of 1KB — longer DRAM bursts / better row locality, same total bytes in
// flight per SM (28 warps x 12 batched loads = 336, same as R7's 56 x 6).
// Slice start rotated per CTA to spread the instantaneous footprint over
// all 192MB. Single launch; per-b ticket finalizes out[b] (32 CTAs/b).
__global__ __launch_bounds__(256, 7) void fused_kernel(
    const float* __restrict__ feat_f_map,
    const float* __restrict__ oct_maps,
    const float* __restrict__ head_w,
    const float* __restrict__ head_b,
    float* __restrict__ out)
{
    const int gid  = blockIdx.x;          // 0..511
    const int b    = gid >> 5;            // / 32
    const int cg   = gid & 31;            // % 32
    const int warp = threadIdx.x >> 5;    // 0..7
    const int lane = threadIdx.x & 31;
    const int c0   = cg * CG + warp * 2;  // this warp's channel pair (c0, c0+1)
    const int s0   = gid % NSL;           // slice rotation offset

    const size_t bc_off = ((size_t)(b * CCH + c0)) << 8;   // *HWN

    // feat_f segments for both channels: 2KB contiguous
    float sff0, sff1;
    {
        const float4* p4 = (const float4*)(feat_f_map + bc_off);
        float4 a0 = p4[lane],      a1 = p4[lane + 32];   // channel c0
        float4 b0 = p4[lane + 64], b1 = p4[lane + 96];   // channel c0+1
        float s = ((a0.x + a0.y) + (a0.z + a0.w))
                + ((a1.x + a1.y) + (a1.z + a1.w));
        float r = ((b0.x + b0.y) + (b0.z + b0.w))
                + ((b1.x + b1.y) + (b1.z + b1.w));
        #pragma unroll
        for (int off = 16; off; off >>= 1) {
            s += __shfl_xor_sync(0xffffffffu, s, off);
            r += __shfl_xor_sync(0xffffffffu, r, off);
        }
        sff0 = s; sff1 = r;
    }

    // 24 oct slices (rotated order): per-channel max over slice sums
    float vmax0 = -CUDART_INF_F, vmax1 = -CUDART_INF_F;
    #pragma unroll 3
    for (int i = 0; i < NSL; i++) {
        int s = s0 + i; if (s >= NSL) s -= NSL;
        const float4* p = (const float4*)
            (oct_maps + (size_t)s * SLICE_STRIDE + bc_off);
        float4 a0 = p[lane],      a1 = p[lane + 32];
        float4 b0 = p[lane + 64], b1 = p[lane + 96];
        float t0 = ((a0.x + a0.y) + (a0.z + a0.w))
                 + ((a1.x + a1.y) + (a1.z + a1.w));
        float t1 = ((b0.x + b0.y) + (b0.z + b0.w))
                 + ((b1.x + b1.y) + (b1.z + b1.w));
        #pragma unroll
        for (int off = 16; off; off >>= 1) {
            t0 += __shfl_xor_sync(0xffffffffu, t0, off);
            t1 += __shfl_xor_sync(0xffffffffu, t1, off);
        }
        vmax0 = fmaxf(vmax0, t0);
        vmax1 = fmaxf(vmax1, t1);
    }

    // Head contribution for both channels (lane 0 of each warp) -> shared acc
    __shared__ float    s_acc[CLASSES];
    __shared__ unsigned s_ticket;
    if (threadIdx.x < CLASSES) s_acc[threadIdx.x] = 0.f;
    __syncthreads();

    if (lane == 0) {
        const float inv = 1.0f / (float)HWN;
        const float ff0 = sff0  * inv, fo0 = vmax0 * inv;
        const float ff1 = sff1  * inv, fo1 = vmax1 * inv;
        #pragma unroll
        for (int cl = 0; cl < CLASSES; cl++) {
            const float* w = head_w + cl * FEAT_IN;
            atomicAdd(&s_acc[cl], ff0 * w[c0]       + fo0 * w[CCH + c0]
                                + ff1 * w[c0 + 1]   + fo1 * w[CCH + c0 + 1]);
        }
    }
    __syncthreads();

    if (threadIdx.x < CLASSES)
        atomicAdd(&g_acc[b * CLASSES + threadIdx.x], s_acc[threadIdx.x]);

    // Per-b completion ticket (release: fence before counter increment)
    __threadfence();
    if (threadIdx.x == 0)
        s_ticket = atomicAdd(&g_count[b], 1u);
    __syncthreads();

    if (s_ticket == CTAS_PER_B - 1) {
        // Last CTA of this b: finalize its 3 outputs, restore scratch state.
        if (threadIdx.x < CLASSES) {
            float v = atomicExch(&g_acc[b * CLASSES + threadIdx.x], 0.f);
            out[b * CLASSES + threadIdx.x] = v + head_b[threadIdx.x];
        }
        if (threadIdx.x == 0)
            atomicExch(&g_count[b], 0u);
    }
}

extern "C" void kernel_launch(void* const* d_in, const int* in_sizes, int n_in,
                              void* d_out, int out_size)
{
    const float* feat_f_map = (const float*)d_in[0];  // (16,512,16,16)
    const float* oct_maps   = (const float*)d_in[1];  // (24,16,512,16,16)
    const float* head_w     = (const float*)d_in[2];  // (3,1024)
    const float* head_b     = (const float*)d_in[3];  // (3,)
    float* out = (float*)d_out;                        // (16,3)

    fused_kernel<<<GRID, 256>>>(feat_f_map, oct_maps, head_w, head_b, out);
}

// round 12
// speedup vs baseline: 1.0994x; 1.0994x over previous
#include <cuda_runtime.h>
#include <math_constants.h>

// Problem constants
#define NSL     24
#define BB      16
#define CCH     512
#define HWN     256          // H*W
#define FEAT_IN 1024
#define CLASSES 3
#define CG      4            // c-values per CTA (one per warp, 4 warps)
#define CTAS_PER_B (CCH / CG)       // 128
#define GRID    (BB * CTAS_PER_B)   // 2048
#define SLICE_STRIDE ((size_t)BB * CCH * HWN)   // floats per slice (2M)

// Persistent scratch (zero at module load; each launch restores it to zero).
__device__ float        g_acc[BB * CLASSES];
__device__ unsigned int g_count[BB];

// Fused kernel: 2048 CTAs x 128 threads (4 warps). Warp owns channel c,
// identical per-warp work to the best-measured R7 kernel — but the smaller
// CTA granularity lifts the occupancy cap from 7x8=56 to 16x4=64 warps/SM
// (100% occ; 32 regs x 64 warps = full RF), raising chip-wide outstanding
// loads ~14%. Slice start rotated per CTA to spread the instantaneous DRAM
// footprint over all 192MB. Single launch; per-b ticket finalizes out[b].
__global__ __launch_bounds__(128, 16) void fused_kernel(
    const float* __restrict__ feat_f_map,
    const float* __restrict__ oct_maps,
    const float* __restrict__ head_w,
    const float* __restrict__ head_b,
    float* __restrict__ out)
{
    const int gid  = blockIdx.x;          // 0..2047
    const int b    = gid >> 7;            // / 128
    const int cg   = gid & 127;           // % 128
    const int warp = threadIdx.x >> 5;    // 0..3
    const int lane = threadIdx.x & 31;
    const int c    = cg * CG + warp;      // this warp's channel
    const int s0   = gid % NSL;           // slice rotation offset

    const size_t bc_off = ((size_t)(b * CCH + c)) << 8;   // *HWN

    // feat_f segment: contiguous 1KB
    float sff;
    {
        const float4* p4 = (const float4*)(feat_f_map + bc_off);
        float4 v0 = p4[lane], v1 = p4[lane + 32];
        float s = ((v0.x + v0.y) + (v0.z + v0.w))
                + ((v1.x + v1.y) + (v1.z + v1.w));
        #pragma unroll
        for (int off = 16; off; off >>= 1)
            s += __shfl_xor_sync(0xffffffffu, s, off);
        sff = s;
    }

    // 24 oct slices (rotated order): max over slice sums
    float vmax = -CUDART_INF_F;
    #pragma unroll 3
    for (int i = 0; i < NSL; i++) {
        int s = s0 + i; if (s >= NSL) s -= NSL;
        const float4* p = (const float4*)
            (oct_maps + (size_t)s * SLICE_STRIDE + bc_off);
        float4 v0 = p[lane], v1 = p[lane + 32];
        float t = ((v0.x + v0.y) + (v0.z + v0.w))
                + ((v1.x + v1.y) + (v1.z + v1.w));
        #pragma unroll
        for (int off = 16; off; off >>= 1)
            t += __shfl_xor_sync(0xffffffffu, t, off);
        vmax = fmaxf(vmax, t);
    }

    // Head contribution for this c (lane 0 of each warp) -> shared acc
    __shared__ float    s_acc[CLASSES];
    __shared__ unsigned s_ticket;
    if (threadIdx.x < CLASSES) s_acc[threadIdx.x] = 0.f;
    __syncthreads();

    if (lane == 0) {
        const float inv = 1.0f / (float)HWN;
        const float ff = sff  * inv;      // feat_f[b][c]
        const float fo = vmax * inv;      // feat_o[b][c] = max_s mean_HW
        #pragma unroll
        for (int cl = 0; cl < CLASSES; cl++) {
            const float* w = head_w + cl * FEAT_IN;
            atomicAdd(&s_acc[cl], ff * w[c] + fo * w[CCH + c]);
        }
    }
    __syncthreads();

    if (threadIdx.x < CLASSES)
        atomicAdd(&g_acc[b * CLASSES + threadIdx.x], s_acc[threadIdx.x]);

    // Per-b completion ticket (release: fence before counter increment)
    __threadfence();
    if (threadIdx.x == 0)
        s_ticket = atomicAdd(&g_count[b], 1u);
    __syncthreads();

    if (s_ticket == CTAS_PER_B - 1) {
        // Last CTA of this b: finalize its 3 outputs, restore scratch state.
        if (threadIdx.x < CLASSES) {
            float v = atomicExch(&g_acc[b * CLASSES + threadIdx.x], 0.f);
            out[b * CLASSES + threadIdx.x] = v + head_b[threadIdx.x];
        }
        if (threadIdx.x == 0)
            atomicExch(&g_count[b], 0u);
    }
}

extern "C" void kernel_launch(void* const* d_in, const int* in_sizes, int n_in,
                              void* d_out, int out_size)
{
    const float* feat_f_map = (const float*)d_in[0];  // (16,512,16,16)
    const float* oct_maps   = (const float*)d_in[1];  // (24,16,512,16,16)
    const float* head_w     = (const float*)d_in[2];  // (3,1024)
    const float* head_b     = (const float*)d_in[3];  // (3,)
    float* out = (float*)d_out;                        // (16,3)

    fused_kernel<<<GRID, 128>>>(feat_f_map, oct_maps, head_w, head_b, out);
}